// round 15
// baseline (speedup 1.0000x reference)
#include <cuda_runtime.h>
#include <cuda_bf16.h>
#include <cstdint>
#include <cstddef>

#define BATCH 16
#define D_LAT 256
#define KCODES 1024
#define QSTAGES 4
#define NROWS (BATCH*4096)

#define OFF_RECON 0
#define OFF_IDX   3145728
#define OFF_LOSS  3407872
#define OFF_Q     3407876

#define VQ_MARGIN 0.03f

// ---------------- scratch ----------------
__device__ float g_a1[BATCH*64*128*128];
__device__ float g_a2[BATCH*128*64*64];
__device__ float g_a3[BATCH*256*64*64];
__device__ float g_z [BATCH*256*64*64];
__device__ float g_res[NROWS*D_LAT];
__device__ float g_quant[NROWS*D_LAT];
__device__ int   g_argidx[NROWS];
__device__ float g_cnorm[QSTAGES*KCODES];
__device__ float g_loss[QSTAGES];
__device__ float g_d1[BATCH*128*64*64];
__device__ float g_dt1[BATCH*64*128*128];
// bf16 hi/lo packed operands: A' = [hi|hi|lo], B' = [hi|lo|hi], K=768
__device__ __nv_bfloat16 g_respk[(size_t)NROWS*768];
__device__ __nv_bfloat16 g_cbpk[(size_t)QSTAGES*KCODES*768];
__device__ int g_fixcnt;
__device__ int g_fixrows[NROWS];

// ============ conv 4x4 stride2 pad1 + bias + relu ============
template<int CI, int COB>
__global__ void __launch_bounds__(256) conv_k4s2(const float* __restrict__ in,
        const float* __restrict__ w, const float* __restrict__ bias,
        float* __restrict__ out, int Hi, int Wi, int Ho, int Wo, int Co)
{
    int nb = Co / COB;
    int n  = blockIdx.z / nb, cob = (blockIdx.z % nb) * COB;
    int x0 = blockIdx.x * 32, y0 = blockIdx.y * 32;
    __shared__ __align__(16) float tile[66][68];
    __shared__ float ws[COB*16];
    int tx = threadIdx.x, ty = threadIdx.y;
    int tid = ty*16 + tx;
    float acc[COB][2][2];
    #pragma unroll
    for (int o = 0; o < COB; o++) acc[o][0][0]=acc[o][0][1]=acc[o][1][0]=acc[o][1][1]=0.f;
    const float* inb = in + (size_t)n*CI*Hi*Wi;
    int iy_base = 2*y0 - 1, ix_base = 2*x0 - 1;
    for (int ci = 0; ci < CI; ci++) {
        __syncthreads();
        const float* inc = inb + (size_t)ci*Hi*Wi;
        for (int idx = tid; idx < 66*66; idx += 256) {
            int r = idx / 66, c = idx % 66;
            int iy = iy_base + r, ix = ix_base + c;
            float v = 0.f;
            if ((unsigned)iy < (unsigned)Hi && (unsigned)ix < (unsigned)Wi)
                v = __ldg(&inc[(size_t)iy*Wi + ix]);
            tile[r][c] = v;
        }
        if (tid < COB*16) {
            int o = tid >> 4, k = tid & 15;
            ws[tid] = __ldg(&w[(size_t)((cob+o)*CI + ci)*16 + k]);
        }
        __syncthreads();
        float win[6][6];
        #pragma unroll
        for (int r = 0; r < 6; r++) {
            float4 v = *(const float4*)&tile[4*ty + r][4*tx];
            win[r][0]=v.x; win[r][1]=v.y; win[r][2]=v.z; win[r][3]=v.w;
            win[r][4]=tile[4*ty+r][4*tx+4];
            win[r][5]=tile[4*ty+r][4*tx+5];
        }
        #pragma unroll
        for (int o = 0; o < COB; o++) {
            float wr[16];
            #pragma unroll
            for (int k = 0; k < 16; k++) wr[k] = ws[o*16 + k];
            #pragma unroll
            for (int ky = 0; ky < 4; ky++)
              #pragma unroll
              for (int kx = 0; kx < 4; kx++) {
                float wv = wr[ky*4+kx];
                #pragma unroll
                for (int sy = 0; sy < 2; sy++)
                  #pragma unroll
                  for (int sx = 0; sx < 2; sx++)
                    acc[o][sy][sx] += win[2*sy+ky][2*sx+kx] * wv;
              }
        }
    }
    #pragma unroll
    for (int o = 0; o < COB; o++) {
        float bv = __ldg(&bias[cob+o]);
        #pragma unroll
        for (int sy = 0; sy < 2; sy++)
          #pragma unroll
          for (int sx = 0; sx < 2; sx++) {
            int oy = y0 + 2*ty + sy, ox = x0 + 2*tx + sx;
            out[(((size_t)n*Co + cob+o)*Ho + oy)*Wo + ox] = fmaxf(acc[o][sy][sx] + bv, 0.f);
          }
    }
}

// ============ conv 3x3 s1 p1 on 64x64, 8 co/block, double-buffered ============
template<bool RELU>
__global__ void __launch_bounds__(256) conv3x3g(const float* __restrict__ in,
        const float* __restrict__ w, const float* __restrict__ bias,
        float* __restrict__ out, int Ci, int Co)
{
    __shared__ __align__(16) float tile[2][2][34][36];
    __shared__ float ws[2][2][8][9];
    int cpb = Co >> 3;
    int n = blockIdx.z / cpb, cob = (blockIdx.z % cpb) << 3;
    int x0 = blockIdx.x << 5, y0 = blockIdx.y << 5;
    int tx = threadIdx.x, ty = threadIdx.y;
    int tid = ty*16 + tx;
    int warp = tid >> 5, lane = tid & 31;

    const float* inb = in + (size_t)n*Ci*4096;
    const float* wb  = w + (size_t)cob*Ci*9;

    auto load_phase = [&](int buf, int ci) {
        #pragma unroll
        for (int ch = 0; ch < 2; ch++) {
            const float* base = inb + (size_t)(ci+ch)*4096;
            for (int r = warp; r < 34; r += 8) {
                int iy = y0 - 1 + r;
                bool vy = (unsigned)iy < 64u;
                #pragma unroll
                for (int cc = 0; cc < 2; cc++) {
                    int c = lane + cc*32;
                    if (c < 34) {
                        int ix = x0 - 1 + c;
                        float v = 0.f;
                        if (vy && (unsigned)ix < 64u) v = __ldg(&base[iy*64 + ix]);
                        tile[buf][ch][r][c] = v;
                    }
                }
            }
        }
        if (tid < 144) {
            int ch = tid / 72, rem = tid % 72;
            int o = rem / 9, k = rem % 9;
            ws[buf][ch][o][k] = __ldg(&wb[(size_t)(o*Ci + ci+ch)*9 + k]);
        }
    };

    float acc[8][2][2];
    #pragma unroll
    for (int o = 0; o < 8; o++) { acc[o][0][0]=acc[o][0][1]=acc[o][1][0]=acc[o][1][1]=0.f; }

    load_phase(0, 0);
    for (int ci = 0; ci < Ci; ci += 2) {
        int cur = (ci >> 1) & 1;
        __syncthreads();
        if (ci + 2 < Ci) load_phase(cur ^ 1, ci + 2);
        #pragma unroll
        for (int ch = 0; ch < 2; ch++) {
            float win[4][4];
            #pragma unroll
            for (int r = 0; r < 4; r++) {
                const float2* rp = (const float2*)&tile[cur][ch][2*ty + r][2*tx];
                float2 p0 = rp[0], p1 = rp[1];
                win[r][0]=p0.x; win[r][1]=p0.y; win[r][2]=p1.x; win[r][3]=p1.y;
            }
            #pragma unroll
            for (int o = 0; o < 8; o++) {
                float wr[9];
                #pragma unroll
                for (int k = 0; k < 9; k++) wr[k] = ws[cur][ch][o][k];
                #pragma unroll
                for (int ky = 0; ky < 3; ky++)
                  #pragma unroll
                  for (int kx = 0; kx < 3; kx++) {
                    float wv = wr[ky*3+kx];
                    acc[o][0][0] += win[ky  ][kx  ] * wv;
                    acc[o][0][1] += win[ky  ][kx+1] * wv;
                    acc[o][1][0] += win[ky+1][kx  ] * wv;
                    acc[o][1][1] += win[ky+1][kx+1] * wv;
                  }
            }
        }
    }
    #pragma unroll
    for (int o = 0; o < 8; o++) {
        float bv = __ldg(&bias[cob+o]);
        float* ob = out + ((size_t)n*Co + cob+o)*4096;
        #pragma unroll
        for (int sy = 0; sy < 2; sy++)
          #pragma unroll
          for (int sx = 0; sx < 2; sx++) {
            float v = acc[o][sy][sx] + bv;
            if (RELU) v = fmaxf(v, 0.f);
            ob[(y0 + 2*ty + sy)*64 + x0 + 2*tx + sx] = v;
          }
    }
}

// ============ transposes (nchw2nhwc also emits bf16 hi/lo pack) ============
__global__ void nchw2nhwc(const float* __restrict__ in, float* __restrict__ out) {
    __shared__ float t[32][33];
    int n = blockIdx.z;
    int hw0 = blockIdx.x << 5, d0 = blockIdx.y << 5;
    int tx = threadIdx.x, ty = threadIdx.y;
    const float* ib = in + (size_t)n*256*4096;
    float* ob = out + (size_t)n*4096*256;
    #pragma unroll
    for (int i = 0; i < 32; i += 8)
        t[ty+i][tx] = ib[(size_t)(d0+ty+i)*4096 + hw0 + tx];
    __syncthreads();
    #pragma unroll
    for (int i = 0; i < 32; i += 8) {
        float v = t[tx][ty+i];
        int lrow = hw0 + ty + i;
        int k = d0 + tx;
        ob[(size_t)lrow*256 + k] = v;
        size_t row = (size_t)n*4096 + lrow;
        __nv_bfloat16 h = __float2bfloat16(v);
        __nv_bfloat16 l = __float2bfloat16(v - __bfloat162float(h));
        size_t b = row*768;
        g_respk[b + k]       = h;
        g_respk[b + 256 + k] = h;
        g_respk[b + 512 + k] = l;
    }
}

__global__ void nhwc2nchw(const float* __restrict__ in, float* __restrict__ out) {
    __shared__ float t[32][33];
    int n = blockIdx.z;
    int hw0 = blockIdx.x << 5, d0 = blockIdx.y << 5;
    int tx = threadIdx.x, ty = threadIdx.y;
    const float* ib = in + (size_t)n*4096*256;
    float* ob = out + (size_t)n*256*4096;
    #pragma unroll
    for (int i = 0; i < 32; i += 8)
        t[ty+i][tx] = ib[(size_t)(hw0+ty+i)*256 + d0 + tx];
    __syncthreads();
    #pragma unroll
    for (int i = 0; i < 32; i += 8)
        ob[(size_t)(d0+ty+i)*4096 + hw0 + tx] = t[tx][ty+i];
}

// ============ codebook norms ============
__global__ void cnorm_kernel(const float* __restrict__ cb) {
    int warp = (blockIdx.x*256 + threadIdx.x) >> 5;
    int lane = threadIdx.x & 31;
    if (warp >= QSTAGES*KCODES) return;
    const float* c = cb + (size_t)warp*D_LAT;
    float s = 0.f;
    for (int i = lane; i < D_LAT; i += 32) { float v = __ldg(&c[i]); s += v*v; }
    #pragma unroll
    for (int o = 16; o; o >>= 1) s += __shfl_xor_sync(0xffffffffu, s, o);
    if (lane == 0) g_cnorm[warp] = s;
}

__global__ void vq_init() { if (threadIdx.x < QSTAGES) g_loss[threadIdx.x] = 0.f; }
__global__ void reset_fix() { if (threadIdx.x == 0) g_fixcnt = 0; }

__global__ void loss_final(float* __restrict__ out) {
    if (threadIdx.x < QSTAGES)
        out[OFF_LOSS + threadIdx.x] = g_loss[threadIdx.x] * (1.0f/16777216.0f);
}

// codebook pack (once per run)
__global__ void pack_cb(const float* __restrict__ cbs) {
    int row = blockIdx.x, k = threadIdx.x;
    float x = cbs[(size_t)row*256 + k];
    __nv_bfloat16 h = __float2bfloat16(x);
    __nv_bfloat16 l = __float2bfloat16(x - __bfloat162float(h));
    size_t b = (size_t)row*768;
    g_cbpk[b + k]       = h;
    g_cbpk[b + 256 + k] = l;
    g_cbpk[b + 512 + k] = h;
}

// ---------------- ldmatrix helper ----------------
__device__ __forceinline__ void ldm_x4(uint32_t& r0, uint32_t& r1, uint32_t& r2, uint32_t& r3,
                                       uint32_t saddr) {
    asm volatile("ldmatrix.sync.aligned.m8n8.x4.shared.b16 {%0,%1,%2,%3}, [%4];"
        : "=r"(r0), "=r"(r1), "=r"(r2), "=r"(r3) : "r"(saddr));
}

// ============ VQ argmin via mma.sync bf16 m16n8k16 + ldmatrix (R10-validated) ============
#define AST 72   // smem row stride in bf16
__global__ void __launch_bounds__(256) vq_argmin_mma(int q) {
    __shared__ __align__(16) __nv_bfloat16 As[128*AST];
    __shared__ __align__(16) __nv_bfloat16 Bs[128*AST];
    int tid = threadIdx.x;
    int warp = tid >> 5, lane = tid & 31;
    int g = lane >> 2, tig = lane & 3;
    int row0 = blockIdx.x << 7;

    uint32_t As_b = (uint32_t)__cvta_generic_to_shared(As);
    uint32_t Bs_b = (uint32_t)__cvta_generic_to_shared(Bs);
    uint32_t a_lane_off = ((warp*16 + (lane & 15))*AST + ((lane >> 4) << 3)) * 2;
    uint32_t b_lane_off = (((lane & 7) + ((lane >> 4) & 1)*8)*AST + (((lane >> 3) & 1) << 3)) * 2;

    float b1v[2] = {3.4e38f, 3.4e38f};
    float b2v[2] = {3.4e38f, 3.4e38f};
    int   b1i[2] = {0, 0};

    const float* cn = g_cnorm + q*KCODES;

    for (int nc = 0; nc < 8; nc++) {
        float acc[16][4];
        #pragma unroll
        for (int t = 0; t < 16; t++) { acc[t][0]=acc[t][1]=acc[t][2]=acc[t][3]=0.f; }
        for (int kc = 0; kc < 12; kc++) {
            __syncthreads();
            #pragma unroll
            for (int u = 0; u < 4; u++) {
                int i = tid + u*256;
                int r = i >> 3, kp = i & 7;
                uint4 v = __ldg((const uint4*)(g_respk + (size_t)(row0 + r)*768 + kc*64 + kp*8));
                *(uint4*)(As + r*AST + kp*8) = v;
            }
            #pragma unroll
            for (int u = 0; u < 4; u++) {
                int i = tid + u*256;
                int r = i >> 3, kp = i & 7;
                uint4 v = __ldg((const uint4*)(g_cbpk + (size_t)(q*KCODES + nc*128 + r)*768 + kc*64 + kp*8));
                *(uint4*)(Bs + r*AST + kp*8) = v;
            }
            __syncthreads();
            #pragma unroll
            for (int ks = 0; ks < 4; ks++) {
                int kb = ks*16;
                uint32_t a0, a1, a2, a3;
                ldm_x4(a0, a1, a2, a3, As_b + a_lane_off + kb*2);
                #pragma unroll
                for (int t = 0; t < 16; t += 2) {
                    uint32_t b0a, b1a, b0b, b1b;
                    ldm_x4(b0a, b1a, b0b, b1b,
                           Bs_b + b_lane_off + (t*8*AST + kb)*2);
                    asm volatile(
                        "mma.sync.aligned.m16n8k16.row.col.f32.bf16.bf16.f32 "
                        "{%0,%1,%2,%3}, {%4,%5,%6,%7}, {%8,%9}, {%0,%1,%2,%3};"
                        : "+f"(acc[t][0]), "+f"(acc[t][1]), "+f"(acc[t][2]), "+f"(acc[t][3])
                        : "r"(a0), "r"(a1), "r"(a2), "r"(a3), "r"(b0a), "r"(b1a));
                    asm volatile(
                        "mma.sync.aligned.m16n8k16.row.col.f32.bf16.bf16.f32 "
                        "{%0,%1,%2,%3}, {%4,%5,%6,%7}, {%8,%9}, {%0,%1,%2,%3};"
                        : "+f"(acc[t+1][0]), "+f"(acc[t+1][1]), "+f"(acc[t+1][2]), "+f"(acc[t+1][3])
                        : "r"(a0), "r"(a1), "r"(a2), "r"(a3), "r"(b0b), "r"(b1b));
                }
            }
        }
        #pragma unroll
        for (int t = 0; t < 16; t++) {
            int c0 = nc*128 + t*8 + tig*2;
            float n0 = __ldg(&cn[c0]), n1 = __ldg(&cn[c0+1]);
            float s00 = n0 - 2.f*acc[t][0];
            float s01 = n1 - 2.f*acc[t][1];
            float s10 = n0 - 2.f*acc[t][2];
            float s11 = n1 - 2.f*acc[t][3];
            if (s00 < b1v[0]) { b2v[0]=b1v[0]; b1v[0]=s00; b1i[0]=c0; }   else if (s00 < b2v[0]) b2v[0]=s00;
            if (s01 < b1v[0]) { b2v[0]=b1v[0]; b1v[0]=s01; b1i[0]=c0+1; } else if (s01 < b2v[0]) b2v[0]=s01;
            if (s10 < b1v[1]) { b2v[1]=b1v[1]; b1v[1]=s10; b1i[1]=c0; }   else if (s10 < b2v[1]) b2v[1]=s10;
            if (s11 < b1v[1]) { b2v[1]=b1v[1]; b1v[1]=s11; b1i[1]=c0+1; } else if (s11 < b2v[1]) b2v[1]=s11;
        }
    }
    #pragma unroll
    for (int off = 1; off <= 2; off <<= 1) {
        #pragma unroll
        for (int s = 0; s < 2; s++) {
            float o1 = __shfl_xor_sync(0xffffffffu, b1v[s], off);
            float o2 = __shfl_xor_sync(0xffffffffu, b2v[s], off);
            int   oi = __shfl_xor_sync(0xffffffffu, b1i[s], off);
            if (o1 < b1v[s]) { b2v[s] = fminf(b1v[s], o2); b1v[s] = o1; b1i[s] = oi; }
            else             { b2v[s] = fminf(b2v[s], fminf(o1, o2)); }
        }
    }
    if (tig == 0) {
        #pragma unroll
        for (int s = 0; s < 2; s++) {
            int row = row0 + warp*16 + g + s*8;
            g_argidx[row] = b1i[s];
            if (b2v[s] - b1v[s] < VQ_MARGIN) {
                int e = atomicAdd(&g_fixcnt, 1);
                g_fixrows[e] = row;
            }
        }
    }
}

// ============ exact fp32 rescore for ambiguous rows ============
__global__ void __launch_bounds__(256) vq_fixup(const float* __restrict__ cb, int q) {
    int gw = (blockIdx.x*256 + threadIdx.x) >> 5;
    int lane = threadIdx.x & 31;
    int cnt = g_fixcnt;
    int nw = (gridDim.x*256) >> 5;
    for (int e = gw; e < cnt; e += nw) {
        int row = g_fixrows[e];
        const float4* r4 = (const float4*)(g_res + (size_t)row*256);
        float bv = 3.4e38f; int bi = 0;
        for (int c = lane; c < 1024; c += 32) {
            const float4* c4 = (const float4*)(cb + (size_t)c*256);
            float dot = 0.f;
            #pragma unroll 8
            for (int d = 0; d < 64; d++) {
                float4 a = r4[d], b = __ldg(&c4[d]);
                dot += a.x*b.x + a.y*b.y + a.z*b.z + a.w*b.w;
            }
            float s = g_cnorm[q*KCODES + c] - 2.f*dot;
            if (s < bv) { bv = s; bi = c; }
        }
        #pragma unroll
        for (int o = 16; o; o >>= 1) {
            float ov = __shfl_xor_sync(0xffffffffu, bv, o);
            int oi = __shfl_xor_sync(0xffffffffu, bi, o);
            if (ov < bv || (ov == bv && oi < bi)) { bv = ov; bi = oi; }
        }
        if (lane == 0) g_argidx[row] = bi;
    }
}

// ============ VQ update (also emits bf16 pack for next stage) ============
__global__ void __launch_bounds__(256) vq_update(const float* __restrict__ cb,
                                                 float* __restrict__ out, int q, int pack) {
    __shared__ float part[8];
    int warp = threadIdx.x >> 5, lane = threadIdx.x & 31;
    int row = (blockIdx.x << 3) + warp;
    int idx = g_argidx[row];
    float4* r4 = (float4*)(g_res   + ((size_t)row << 8));
    float4* q4 = (float4*)(g_quant + ((size_t)row << 8));
    const float4* c4 = (const float4*)(cb + ((size_t)idx << 8));
    float ls = 0.f;
    #pragma unroll
    for (int v = 0; v < 2; v++) {
        int i = lane + (v << 5);
        float4 rv = r4[i];
        float4 cv = __ldg(&c4[i]);
        float dx = cv.x - rv.x, dy = cv.y - rv.y, dz = cv.z - rv.z, dw = cv.w - rv.w;
        ls += dx*dx + dy*dy + dz*dz + dw*dw;
        float4 qc = make_float4(rv.x + dx, rv.y + dy, rv.z + dz, rv.w + dw);
        if (q) { float4 o = q4[i]; qc.x += o.x; qc.y += o.y; qc.z += o.z; qc.w += o.w; }
        q4[i] = qc;
        float4 nr = make_float4(-dx, -dy, -dz, -dw);
        r4[i] = nr;
        if (pack) {
            __nv_bfloat16 h0 = __float2bfloat16(nr.x), h1 = __float2bfloat16(nr.y);
            __nv_bfloat16 h2 = __float2bfloat16(nr.z), h3 = __float2bfloat16(nr.w);
            __nv_bfloat16 l0 = __float2bfloat16(nr.x - __bfloat162float(h0));
            __nv_bfloat16 l1 = __float2bfloat16(nr.y - __bfloat162float(h1));
            __nv_bfloat16 l2 = __float2bfloat16(nr.z - __bfloat162float(h2));
            __nv_bfloat16 l3 = __float2bfloat16(nr.w - __bfloat162float(h3));
            size_t b = (size_t)row*768 + 4*i;
            __nv_bfloat162* p0 = (__nv_bfloat162*)(g_respk + b);
            __nv_bfloat162* p1 = (__nv_bfloat162*)(g_respk + b + 256);
            __nv_bfloat162* p2 = (__nv_bfloat162*)(g_respk + b + 512);
            __nv_bfloat162 hA; hA.x = h0; hA.y = h1;
            __nv_bfloat162 hB; hB.x = h2; hB.y = h3;
            __nv_bfloat162 lA; lA.x = l0; lA.y = l1;
            __nv_bfloat162 lB; lB.x = l2; lB.y = l3;
            p0[0] = hA; p0[1] = hB;
            p1[0] = hA; p1[1] = hB;
            p2[0] = lA; p2[1] = lB;
        }
    }
    #pragma unroll
    for (int o = 16; o; o >>= 1) ls += __shfl_xor_sync(0xffffffffu, ls, o);
    if (lane == 0) part[warp] = ls;
    __syncthreads();
    if (threadIdx.x == 0) {
        float s = 0.f;
        #pragma unroll
        for (int i = 0; i < 8; i++) s += part[i];
        atomicAdd(&g_loss[q], s);
    }
    if (lane == 0) {
        int b = row >> 12, hw = row & 4095;
        out[OFF_IDX + ((size_t)((b << 2) + q))*4096 + hw] = (float)idx;
    }
}

// ============ transposed conv 4x4 s2 p1, 2x2 output-quad gather, COB co/block ============
template<int CI, int CO, int COB, int ACT>
__global__ void __launch_bounds__(256) convt_k4s2(const float* __restrict__ in,
        const float* __restrict__ w, const float* __restrict__ bias,
        float* __restrict__ out, int Hi, int Wi)
{
    __shared__ float ws[CI*COB*16];
    int nb = CO / COB;
    int n = blockIdx.z / nb, cop = (blockIdx.z % nb) * COB;
    int tid = threadIdx.y*16 + threadIdx.x;
    for (int k = tid; k < CI*COB*16; k += 256) {
        int ci = k / (COB*16);
        int rem = k % (COB*16);
        int o = rem >> 4, kk = rem & 15;
        ws[k] = __ldg(&w[(size_t)(ci*CO + cop + o)*16 + kk]);
    }
    __syncthreads();
    int i = blockIdx.y*16 + threadIdx.y - 1;
    int j = blockIdx.x*16 + threadIdx.x - 1;
    if (i > Hi-1 || j > Wi-1) return;
    int Ho = Hi*2, Wo = Wi*2;
    bool my0 = (i >= 0), my1 = (i < Hi-1);
    bool mx0 = (j >= 0), mx1 = (j < Wi-1);
    int ic = my0 ? i : 0, jc = mx0 ? j : 0;
    int off00 = ic*Wi + jc;
    int off01 = ic*Wi + (mx1 ? j+1 : jc);
    int off10 = (my1 ? i+1 : ic)*Wi + jc;
    int off11 = (my1 ? i+1 : ic)*Wi + (mx1 ? j+1 : jc);
    bool m00 = my0 && mx0, m01 = my0 && mx1, m10 = my1 && mx0, m11 = my1 && mx1;
    const float* p = in + (size_t)n*CI*Hi*Wi;
    float a00[COB], a01[COB], a10[COB], a11[COB];
    #pragma unroll
    for (int o = 0; o < COB; o++) { a00[o]=0.f; a01[o]=0.f; a10[o]=0.f; a11[o]=0.f; }
    for (int ci = 0; ci < CI; ci++) {
        float v00 = m00 ? __ldg(p + off00) : 0.f;
        float v01 = m01 ? __ldg(p + off01) : 0.f;
        float v10 = m10 ? __ldg(p + off10) : 0.f;
        float v11 = m11 ? __ldg(p + off11) : 0.f;
        #pragma unroll
        for (int o = 0; o < COB; o++) {
            const float* wc = &ws[(ci*COB + o) << 4];
            a00[o] += v00*wc[10] + v01*wc[8]  + v10*wc[2]  + v11*wc[0];
            a01[o] += v00*wc[11] + v01*wc[9]  + v10*wc[3]  + v11*wc[1];
            a10[o] += v00*wc[14] + v01*wc[12] + v10*wc[6]  + v11*wc[4];
            a11[o] += v00*wc[15] + v01*wc[13] + v10*wc[7]  + v11*wc[5];
        }
        p += Hi*Wi;
    }
    int oy0 = 2*i+1, ox0 = 2*j+1;
    bool wy0 = (oy0 >= 0), wy1 = (2*i+2 < Ho);
    bool wx0 = (ox0 >= 0), wx1 = (2*j+2 < Wo);
    #pragma unroll
    for (int o = 0; o < COB; o++) {
        float bv = __ldg(&bias[cop + o]);
        float r00 = a00[o] + bv, r01 = a01[o] + bv, r10 = a10[o] + bv, r11 = a11[o] + bv;
        if (ACT == 0) { r00=fmaxf(r00,0.f); r01=fmaxf(r01,0.f); r10=fmaxf(r10,0.f); r11=fmaxf(r11,0.f); }
        else { r00=tanhf(r00); r01=tanhf(r01); r10=tanhf(r10); r11=tanhf(r11); }
        float* ob = out + ((size_t)n*CO + cop + o)*Ho*Wo;
        if (wy0 && wx0) ob[oy0*Wo + ox0]       = r00;
        if (wy0 && wx1) ob[oy0*Wo + ox0+1]     = r01;
        if (wy1 && wx0) ob[(oy0+1)*Wo + ox0]   = r10;
        if (wy1 && wx1) ob[(oy0+1)*Wo + ox0+1] = r11;
    }
}

// ---------------- launch ----------------
extern "C" void kernel_launch(void* const* d_in, const int* in_sizes, int n_in,
                              void* d_out, int out_size)
{
    const float* x    = (const float*)d_in[0];
    const float* ew1  = (const float*)d_in[1];  const float* eb1 = (const float*)d_in[2];
    const float* ew2  = (const float*)d_in[3];  const float* eb2 = (const float*)d_in[4];
    const float* ew3  = (const float*)d_in[5];  const float* eb3 = (const float*)d_in[6];
    const float* ew4  = (const float*)d_in[7];  const float* eb4 = (const float*)d_in[8];
    const float* cbs  = (const float*)d_in[9];
    const float* dw1  = (const float*)d_in[10]; const float* db1 = (const float*)d_in[11];
    const float* dtw1 = (const float*)d_in[12]; const float* dtb1= (const float*)d_in[13];
    const float* dtw2 = (const float*)d_in[14]; const float* dtb2= (const float*)d_in[15];
    float* out = (float*)d_out;

    float *a1, *a2, *a3, *z, *quant, *d1, *dt1, *res;
    cudaGetSymbolAddress((void**)&a1,    g_a1);
    cudaGetSymbolAddress((void**)&a2,    g_a2);
    cudaGetSymbolAddress((void**)&a3,    g_a3);
    cudaGetSymbolAddress((void**)&z,     g_z);
    cudaGetSymbolAddress((void**)&res,   g_res);
    cudaGetSymbolAddress((void**)&quant, g_quant);
    cudaGetSymbolAddress((void**)&d1,    g_d1);
    cudaGetSymbolAddress((void**)&dt1,   g_dt1);

    dim3 b16(16, 16);

    // encoder
    conv_k4s2<3,  8><<<dim3(4, 4, BATCH*8 ), b16>>>(x,  ew1, eb1, a1, 256, 256, 128, 128, 64);
    conv_k4s2<64, 8><<<dim3(2, 2, BATCH*16), b16>>>(a1, ew2, eb2, a2, 128, 128,  64,  64, 128);
    conv3x3g<true ><<<dim3(2, 2, 32*BATCH), b16>>>(a2, ew3, eb3, a3, 128, 256);
    conv3x3g<false><<<dim3(2, 2, 32*BATCH), b16>>>(a3, ew4, eb4, z,  256, 256);

    // VQ
    nchw2nhwc<<<dim3(128, 8, BATCH), dim3(32, 8)>>>(z, res);
    cnorm_kernel<<<512, 256>>>(cbs);
    vq_init<<<1, 32>>>();
    pack_cb<<<QSTAGES*KCODES, 256>>>(cbs);
    for (int q = 0; q < QSTAGES; q++) {
        const float* cbq = cbs + (size_t)q * KCODES * D_LAT;
        reset_fix<<<1, 32>>>();
        vq_argmin_mma<<<NROWS/128, 256>>>(q);
        vq_fixup<<<64, 256>>>(cbq, q);
        vq_update<<<NROWS/8, 256>>>(cbq, out, q, q < QSTAGES-1 ? 1 : 0);
    }
    loss_final<<<1, 32>>>(out);
    nhwc2nchw<<<dim3(128, 8, BATCH), dim3(32, 8)>>>(quant, out + OFF_Q);

    // decoder
    conv3x3g<true><<<dim3(2, 2, 16*BATCH), b16>>>(out + OFF_Q, dw1, db1, d1, 256, 128);
    convt_k4s2<128, 64, 2, 0><<<dim3(5, 5, BATCH*32), b16>>>(d1,  dtw1, dtb1, dt1, 64, 64);
    convt_k4s2<64,  3, 1, 1><<<dim3(9, 9, BATCH*3 ), b16>>>(dt1, dtw2, dtb2, out + OFF_RECON, 128, 128);
}

// round 16
// speedup vs baseline: 1.0811x; 1.0811x over previous
#include <cuda_runtime.h>
#include <cuda_bf16.h>
#include <cstdint>
#include <cstddef>

#define BATCH 16
#define D_LAT 256
#define KCODES 1024
#define QSTAGES 4
#define NROWS (BATCH*4096)

#define OFF_RECON 0
#define OFF_IDX   3145728
#define OFF_LOSS  3407872
#define OFF_Q     3407876

#define VQ_MARGIN 0.03f

// ---------------- scratch ----------------
__device__ float g_a1[BATCH*64*128*128];
__device__ float g_a2[BATCH*128*64*64];
__device__ float g_a3[BATCH*256*64*64];
__device__ float g_z [BATCH*256*64*64];
__device__ float g_res[NROWS*D_LAT];
__device__ float g_quant[NROWS*D_LAT];
__device__ int   g_argidx[NROWS];
__device__ float g_cnorm[QSTAGES*KCODES];
__device__ float g_loss[QSTAGES];
__device__ float g_d1[BATCH*128*64*64];
__device__ float g_dt1[BATCH*64*128*128];
// bf16 hi/lo packed operands: A' = [hi|hi|lo], B' = [hi|lo|hi], K=768
__device__ __nv_bfloat16 g_respk[(size_t)NROWS*768];
__device__ __nv_bfloat16 g_cbpk[(size_t)QSTAGES*KCODES*768];
__device__ int g_fixcnt;
__device__ int g_fixrows[NROWS];

// ============ conv 4x4 stride2 pad1 + bias + relu ============
template<int CI, int COB>
__global__ void __launch_bounds__(256) conv_k4s2(const float* __restrict__ in,
        const float* __restrict__ w, const float* __restrict__ bias,
        float* __restrict__ out, int Hi, int Wi, int Ho, int Wo, int Co)
{
    int nb = Co / COB;
    int n  = blockIdx.z / nb, cob = (blockIdx.z % nb) * COB;
    int x0 = blockIdx.x * 32, y0 = blockIdx.y * 32;
    __shared__ __align__(16) float tile[66][68];
    __shared__ float ws[COB*16];
    int tx = threadIdx.x, ty = threadIdx.y;
    int tid = ty*16 + tx;
    float acc[COB][2][2];
    #pragma unroll
    for (int o = 0; o < COB; o++) acc[o][0][0]=acc[o][0][1]=acc[o][1][0]=acc[o][1][1]=0.f;
    const float* inb = in + (size_t)n*CI*Hi*Wi;
    int iy_base = 2*y0 - 1, ix_base = 2*x0 - 1;
    for (int ci = 0; ci < CI; ci++) {
        __syncthreads();
        const float* inc = inb + (size_t)ci*Hi*Wi;
        for (int idx = tid; idx < 66*66; idx += 256) {
            int r = idx / 66, c = idx % 66;
            int iy = iy_base + r, ix = ix_base + c;
            float v = 0.f;
            if ((unsigned)iy < (unsigned)Hi && (unsigned)ix < (unsigned)Wi)
                v = __ldg(&inc[(size_t)iy*Wi + ix]);
            tile[r][c] = v;
        }
        if (tid < COB*16) {
            int o = tid >> 4, k = tid & 15;
            ws[tid] = __ldg(&w[(size_t)((cob+o)*CI + ci)*16 + k]);
        }
        __syncthreads();
        float win[6][6];
        #pragma unroll
        for (int r = 0; r < 6; r++) {
            float4 v = *(const float4*)&tile[4*ty + r][4*tx];
            win[r][0]=v.x; win[r][1]=v.y; win[r][2]=v.z; win[r][3]=v.w;
            win[r][4]=tile[4*ty+r][4*tx+4];
            win[r][5]=tile[4*ty+r][4*tx+5];
        }
        #pragma unroll
        for (int o = 0; o < COB; o++) {
            float wr[16];
            #pragma unroll
            for (int k = 0; k < 16; k++) wr[k] = ws[o*16 + k];
            #pragma unroll
            for (int ky = 0; ky < 4; ky++)
              #pragma unroll
              for (int kx = 0; kx < 4; kx++) {
                float wv = wr[ky*4+kx];
                #pragma unroll
                for (int sy = 0; sy < 2; sy++)
                  #pragma unroll
                  for (int sx = 0; sx < 2; sx++)
                    acc[o][sy][sx] += win[2*sy+ky][2*sx+kx] * wv;
              }
        }
    }
    #pragma unroll
    for (int o = 0; o < COB; o++) {
        float bv = __ldg(&bias[cob+o]);
        #pragma unroll
        for (int sy = 0; sy < 2; sy++)
          #pragma unroll
          for (int sx = 0; sx < 2; sx++) {
            int oy = y0 + 2*ty + sy, ox = x0 + 2*tx + sx;
            out[(((size_t)n*Co + cob+o)*Ho + oy)*Wo + ox] = fmaxf(acc[o][sy][sx] + bv, 0.f);
          }
    }
}

// ============ conv 3x3 s1 p1 on 64x64, 8 co/block, double-buffered, 4 blocks/SM ============
template<bool RELU>
__global__ void __launch_bounds__(256, 4) conv3x3g(const float* __restrict__ in,
        const float* __restrict__ w, const float* __restrict__ bias,
        float* __restrict__ out, int Ci, int Co)
{
    __shared__ __align__(16) float tile[2][2][34][36];
    __shared__ float ws[2][2][8][9];
    int cpb = Co >> 3;
    int n = blockIdx.z / cpb, cob = (blockIdx.z % cpb) << 3;
    int x0 = blockIdx.x << 5, y0 = blockIdx.y << 5;
    int tx = threadIdx.x, ty = threadIdx.y;
    int tid = ty*16 + tx;
    int warp = tid >> 5, lane = tid & 31;

    const float* inb = in + (size_t)n*Ci*4096;
    const float* wb  = w + (size_t)cob*Ci*9;

    auto load_phase = [&](int buf, int ci) {
        #pragma unroll
        for (int ch = 0; ch < 2; ch++) {
            const float* base = inb + (size_t)(ci+ch)*4096;
            for (int r = warp; r < 34; r += 8) {
                int iy = y0 - 1 + r;
                bool vy = (unsigned)iy < 64u;
                #pragma unroll
                for (int cc = 0; cc < 2; cc++) {
                    int c = lane + cc*32;
                    if (c < 34) {
                        int ix = x0 - 1 + c;
                        float v = 0.f;
                        if (vy && (unsigned)ix < 64u) v = __ldg(&base[iy*64 + ix]);
                        tile[buf][ch][r][c] = v;
                    }
                }
            }
        }
        if (tid < 144) {
            int ch = tid / 72, rem = tid % 72;
            int o = rem / 9, k = rem % 9;
            ws[buf][ch][o][k] = __ldg(&wb[(size_t)(o*Ci + ci+ch)*9 + k]);
        }
    };

    float acc[8][2][2];
    #pragma unroll
    for (int o = 0; o < 8; o++) { acc[o][0][0]=acc[o][0][1]=acc[o][1][0]=acc[o][1][1]=0.f; }

    load_phase(0, 0);
    for (int ci = 0; ci < Ci; ci += 2) {
        int cur = (ci >> 1) & 1;
        __syncthreads();
        if (ci + 2 < Ci) load_phase(cur ^ 1, ci + 2);
        #pragma unroll
        for (int ch = 0; ch < 2; ch++) {
            float win[4][4];
            #pragma unroll
            for (int r = 0; r < 4; r++) {
                const float2* rp = (const float2*)&tile[cur][ch][2*ty + r][2*tx];
                float2 p0 = rp[0], p1 = rp[1];
                win[r][0]=p0.x; win[r][1]=p0.y; win[r][2]=p1.x; win[r][3]=p1.y;
            }
            #pragma unroll
            for (int o = 0; o < 8; o++) {
                float wr[9];
                #pragma unroll
                for (int k = 0; k < 9; k++) wr[k] = ws[cur][ch][o][k];
                #pragma unroll
                for (int ky = 0; ky < 3; ky++)
                  #pragma unroll
                  for (int kx = 0; kx < 3; kx++) {
                    float wv = wr[ky*3+kx];
                    acc[o][0][0] += win[ky  ][kx  ] * wv;
                    acc[o][0][1] += win[ky  ][kx+1] * wv;
                    acc[o][1][0] += win[ky+1][kx  ] * wv;
                    acc[o][1][1] += win[ky+1][kx+1] * wv;
                  }
            }
        }
    }
    #pragma unroll
    for (int o = 0; o < 8; o++) {
        float bv = __ldg(&bias[cob+o]);
        float* ob = out + ((size_t)n*Co + cob+o)*4096;
        #pragma unroll
        for (int sy = 0; sy < 2; sy++)
          #pragma unroll
          for (int sx = 0; sx < 2; sx++) {
            float v = acc[o][sy][sx] + bv;
            if (RELU) v = fmaxf(v, 0.f);
            ob[(y0 + 2*ty + sy)*64 + x0 + 2*tx + sx] = v;
          }
    }
}

// ============ transposes (nchw2nhwc also emits bf16 hi/lo pack) ============
__global__ void nchw2nhwc(const float* __restrict__ in, float* __restrict__ out) {
    __shared__ float t[32][33];
    int n = blockIdx.z;
    int hw0 = blockIdx.x << 5, d0 = blockIdx.y << 5;
    int tx = threadIdx.x, ty = threadIdx.y;
    const float* ib = in + (size_t)n*256*4096;
    float* ob = out + (size_t)n*4096*256;
    #pragma unroll
    for (int i = 0; i < 32; i += 8)
        t[ty+i][tx] = ib[(size_t)(d0+ty+i)*4096 + hw0 + tx];
    __syncthreads();
    #pragma unroll
    for (int i = 0; i < 32; i += 8) {
        float v = t[tx][ty+i];
        int lrow = hw0 + ty + i;
        int k = d0 + tx;
        ob[(size_t)lrow*256 + k] = v;
        size_t row = (size_t)n*4096 + lrow;
        __nv_bfloat16 h = __float2bfloat16(v);
        __nv_bfloat16 l = __float2bfloat16(v - __bfloat162float(h));
        size_t b = row*768;
        g_respk[b + k]       = h;
        g_respk[b + 256 + k] = h;
        g_respk[b + 512 + k] = l;
    }
}

__global__ void nhwc2nchw(const float* __restrict__ in, float* __restrict__ out) {
    __shared__ float t[32][33];
    int n = blockIdx.z;
    int hw0 = blockIdx.x << 5, d0 = blockIdx.y << 5;
    int tx = threadIdx.x, ty = threadIdx.y;
    const float* ib = in + (size_t)n*4096*256;
    float* ob = out + (size_t)n*256*4096;
    #pragma unroll
    for (int i = 0; i < 32; i += 8)
        t[ty+i][tx] = ib[(size_t)(hw0+ty+i)*256 + d0 + tx];
    __syncthreads();
    #pragma unroll
    for (int i = 0; i < 32; i += 8)
        ob[(size_t)(d0+ty+i)*4096 + hw0 + tx] = t[tx][ty+i];
}

// ============ codebook norms ============
__global__ void cnorm_kernel(const float* __restrict__ cb) {
    int warp = (blockIdx.x*256 + threadIdx.x) >> 5;
    int lane = threadIdx.x & 31;
    if (warp >= QSTAGES*KCODES) return;
    const float* c = cb + (size_t)warp*D_LAT;
    float s = 0.f;
    for (int i = lane; i < D_LAT; i += 32) { float v = __ldg(&c[i]); s += v*v; }
    #pragma unroll
    for (int o = 16; o; o >>= 1) s += __shfl_xor_sync(0xffffffffu, s, o);
    if (lane == 0) g_cnorm[warp] = s;
}

__global__ void vq_init() { if (threadIdx.x < QSTAGES) g_loss[threadIdx.x] = 0.f; }
__global__ void reset_fix() { if (threadIdx.x == 0) g_fixcnt = 0; }

__global__ void loss_final(float* __restrict__ out) {
    if (threadIdx.x < QSTAGES)
        out[OFF_LOSS + threadIdx.x] = g_loss[threadIdx.x] * (1.0f/16777216.0f);
}

// codebook pack (once per run)
__global__ void pack_cb(const float* __restrict__ cbs) {
    int row = blockIdx.x, k = threadIdx.x;
    float x = cbs[(size_t)row*256 + k];
    __nv_bfloat16 h = __float2bfloat16(x);
    __nv_bfloat16 l = __float2bfloat16(x - __bfloat162float(h));
    size_t b = (size_t)row*768;
    g_cbpk[b + k]       = h;
    g_cbpk[b + 256 + k] = l;
    g_cbpk[b + 512 + k] = h;
}

// ---------------- ldmatrix helper ----------------
__device__ __forceinline__ void ldm_x4(uint32_t& r0, uint32_t& r1, uint32_t& r2, uint32_t& r3,
                                       uint32_t saddr) {
    asm volatile("ldmatrix.sync.aligned.m8n8.x4.shared.b16 {%0,%1,%2,%3}, [%4];"
        : "=r"(r0), "=r"(r1), "=r"(r2), "=r"(r3) : "r"(saddr));
}

// ============ VQ argmin via mma.sync bf16 m16n8k16 + ldmatrix (R10-validated) ============
#define AST 72   // smem row stride in bf16
__global__ void __launch_bounds__(256) vq_argmin_mma(int q) {
    __shared__ __align__(16) __nv_bfloat16 As[128*AST];
    __shared__ __align__(16) __nv_bfloat16 Bs[128*AST];
    int tid = threadIdx.x;
    int warp = tid >> 5, lane = tid & 31;
    int g = lane >> 2, tig = lane & 3;
    int row0 = blockIdx.x << 7;

    uint32_t As_b = (uint32_t)__cvta_generic_to_shared(As);
    uint32_t Bs_b = (uint32_t)__cvta_generic_to_shared(Bs);
    uint32_t a_lane_off = ((warp*16 + (lane & 15))*AST + ((lane >> 4) << 3)) * 2;
    uint32_t b_lane_off = (((lane & 7) + ((lane >> 4) & 1)*8)*AST + (((lane >> 3) & 1) << 3)) * 2;

    float b1v[2] = {3.4e38f, 3.4e38f};
    float b2v[2] = {3.4e38f, 3.4e38f};
    int   b1i[2] = {0, 0};

    const float* cn = g_cnorm + q*KCODES;

    for (int nc = 0; nc < 8; nc++) {
        float acc[16][4];
        #pragma unroll
        for (int t = 0; t < 16; t++) { acc[t][0]=acc[t][1]=acc[t][2]=acc[t][3]=0.f; }
        for (int kc = 0; kc < 12; kc++) {
            __syncthreads();
            #pragma unroll
            for (int u = 0; u < 4; u++) {
                int i = tid + u*256;
                int r = i >> 3, kp = i & 7;
                uint4 v = __ldg((const uint4*)(g_respk + (size_t)(row0 + r)*768 + kc*64 + kp*8));
                *(uint4*)(As + r*AST + kp*8) = v;
            }
            #pragma unroll
            for (int u = 0; u < 4; u++) {
                int i = tid + u*256;
                int r = i >> 3, kp = i & 7;
                uint4 v = __ldg((const uint4*)(g_cbpk + (size_t)(q*KCODES + nc*128 + r)*768 + kc*64 + kp*8));
                *(uint4*)(Bs + r*AST + kp*8) = v;
            }
            __syncthreads();
            #pragma unroll
            for (int ks = 0; ks < 4; ks++) {
                int kb = ks*16;
                uint32_t a0, a1, a2, a3;
                ldm_x4(a0, a1, a2, a3, As_b + a_lane_off + kb*2);
                #pragma unroll
                for (int t = 0; t < 16; t += 2) {
                    uint32_t b0a, b1a, b0b, b1b;
                    ldm_x4(b0a, b1a, b0b, b1b,
                           Bs_b + b_lane_off + (t*8*AST + kb)*2);
                    asm volatile(
                        "mma.sync.aligned.m16n8k16.row.col.f32.bf16.bf16.f32 "
                        "{%0,%1,%2,%3}, {%4,%5,%6,%7}, {%8,%9}, {%0,%1,%2,%3};"
                        : "+f"(acc[t][0]), "+f"(acc[t][1]), "+f"(acc[t][2]), "+f"(acc[t][3])
                        : "r"(a0), "r"(a1), "r"(a2), "r"(a3), "r"(b0a), "r"(b1a));
                    asm volatile(
                        "mma.sync.aligned.m16n8k16.row.col.f32.bf16.bf16.f32 "
                        "{%0,%1,%2,%3}, {%4,%5,%6,%7}, {%8,%9}, {%0,%1,%2,%3};"
                        : "+f"(acc[t+1][0]), "+f"(acc[t+1][1]), "+f"(acc[t+1][2]), "+f"(acc[t+1][3])
                        : "r"(a0), "r"(a1), "r"(a2), "r"(a3), "r"(b0b), "r"(b1b));
                }
            }
        }
        #pragma unroll
        for (int t = 0; t < 16; t++) {
            int c0 = nc*128 + t*8 + tig*2;
            float n0 = __ldg(&cn[c0]), n1 = __ldg(&cn[c0+1]);
            float s00 = n0 - 2.f*acc[t][0];
            float s01 = n1 - 2.f*acc[t][1];
            float s10 = n0 - 2.f*acc[t][2];
            float s11 = n1 - 2.f*acc[t][3];
            if (s00 < b1v[0]) { b2v[0]=b1v[0]; b1v[0]=s00; b1i[0]=c0; }   else if (s00 < b2v[0]) b2v[0]=s00;
            if (s01 < b1v[0]) { b2v[0]=b1v[0]; b1v[0]=s01; b1i[0]=c0+1; } else if (s01 < b2v[0]) b2v[0]=s01;
            if (s10 < b1v[1]) { b2v[1]=b1v[1]; b1v[1]=s10; b1i[1]=c0; }   else if (s10 < b2v[1]) b2v[1]=s10;
            if (s11 < b1v[1]) { b2v[1]=b1v[1]; b1v[1]=s11; b1i[1]=c0+1; } else if (s11 < b2v[1]) b2v[1]=s11;
        }
    }
    #pragma unroll
    for (int off = 1; off <= 2; off <<= 1) {
        #pragma unroll
        for (int s = 0; s < 2; s++) {
            float o1 = __shfl_xor_sync(0xffffffffu, b1v[s], off);
            float o2 = __shfl_xor_sync(0xffffffffu, b2v[s], off);
            int   oi = __shfl_xor_sync(0xffffffffu, b1i[s], off);
            if (o1 < b1v[s]) { b2v[s] = fminf(b1v[s], o2); b1v[s] = o1; b1i[s] = oi; }
            else             { b2v[s] = fminf(b2v[s], fminf(o1, o2)); }
        }
    }
    if (tig == 0) {
        #pragma unroll
        for (int s = 0; s < 2; s++) {
            int row = row0 + warp*16 + g + s*8;
            g_argidx[row] = b1i[s];
            if (b2v[s] - b1v[s] < VQ_MARGIN) {
                int e = atomicAdd(&g_fixcnt, 1);
                g_fixrows[e] = row;
            }
        }
    }
}

// ============ exact fp32 rescore for ambiguous rows ============
__global__ void __launch_bounds__(256) vq_fixup(const float* __restrict__ cb, int q) {
    int gw = (blockIdx.x*256 + threadIdx.x) >> 5;
    int lane = threadIdx.x & 31;
    int cnt = g_fixcnt;
    int nw = (gridDim.x*256) >> 5;
    for (int e = gw; e < cnt; e += nw) {
        int row = g_fixrows[e];
        const float4* r4 = (const float4*)(g_res + (size_t)row*256);
        float bv = 3.4e38f; int bi = 0;
        for (int c = lane; c < 1024; c += 32) {
            const float4* c4 = (const float4*)(cb + (size_t)c*256);
            float dot = 0.f;
            #pragma unroll 8
            for (int d = 0; d < 64; d++) {
                float4 a = r4[d], b = __ldg(&c4[d]);
                dot += a.x*b.x + a.y*b.y + a.z*b.z + a.w*b.w;
            }
            float s = g_cnorm[q*KCODES + c] - 2.f*dot;
            if (s < bv) { bv = s; bi = c; }
        }
        #pragma unroll
        for (int o = 16; o; o >>= 1) {
            float ov = __shfl_xor_sync(0xffffffffu, bv, o);
            int oi = __shfl_xor_sync(0xffffffffu, bi, o);
            if (ov < bv || (ov == bv && oi < bi)) { bv = ov; bi = oi; }
        }
        if (lane == 0) g_argidx[row] = bi;
    }
}

// ============ VQ update (also emits bf16 pack for next stage) ============
__global__ void __launch_bounds__(256) vq_update(const float* __restrict__ cb,
                                                 float* __restrict__ out, int q, int pack) {
    __shared__ float part[8];
    int warp = threadIdx.x >> 5, lane = threadIdx.x & 31;
    int row = (blockIdx.x << 3) + warp;
    int idx = g_argidx[row];
    float4* r4 = (float4*)(g_res   + ((size_t)row << 8));
    float4* q4 = (float4*)(g_quant + ((size_t)row << 8));
    const float4* c4 = (const float4*)(cb + ((size_t)idx << 8));
    float ls = 0.f;
    #pragma unroll
    for (int v = 0; v < 2; v++) {
        int i = lane + (v << 5);
        float4 rv = r4[i];
        float4 cv = __ldg(&c4[i]);
        float dx = cv.x - rv.x, dy = cv.y - rv.y, dz = cv.z - rv.z, dw = cv.w - rv.w;
        ls += dx*dx + dy*dy + dz*dz + dw*dw;
        float4 qc = make_float4(rv.x + dx, rv.y + dy, rv.z + dz, rv.w + dw);
        if (q) { float4 o = q4[i]; qc.x += o.x; qc.y += o.y; qc.z += o.z; qc.w += o.w; }
        q4[i] = qc;
        float4 nr = make_float4(-dx, -dy, -dz, -dw);
        r4[i] = nr;
        if (pack) {
            __nv_bfloat16 h0 = __float2bfloat16(nr.x), h1 = __float2bfloat16(nr.y);
            __nv_bfloat16 h2 = __float2bfloat16(nr.z), h3 = __float2bfloat16(nr.w);
            __nv_bfloat16 l0 = __float2bfloat16(nr.x - __bfloat162float(h0));
            __nv_bfloat16 l1 = __float2bfloat16(nr.y - __bfloat162float(h1));
            __nv_bfloat16 l2 = __float2bfloat16(nr.z - __bfloat162float(h2));
            __nv_bfloat16 l3 = __float2bfloat16(nr.w - __bfloat162float(h3));
            size_t b = (size_t)row*768 + 4*i;
            __nv_bfloat162* p0 = (__nv_bfloat162*)(g_respk + b);
            __nv_bfloat162* p1 = (__nv_bfloat162*)(g_respk + b + 256);
            __nv_bfloat162* p2 = (__nv_bfloat162*)(g_respk + b + 512);
            __nv_bfloat162 hA; hA.x = h0; hA.y = h1;
            __nv_bfloat162 hB; hB.x = h2; hB.y = h3;
            __nv_bfloat162 lA; lA.x = l0; lA.y = l1;
            __nv_bfloat162 lB; lB.x = l2; lB.y = l3;
            p0[0] = hA; p0[1] = hB;
            p1[0] = hA; p1[1] = hB;
            p2[0] = lA; p2[1] = lB;
        }
    }
    #pragma unroll
    for (int o = 16; o; o >>= 1) ls += __shfl_xor_sync(0xffffffffu, ls, o);
    if (lane == 0) part[warp] = ls;
    __syncthreads();
    if (threadIdx.x == 0) {
        float s = 0.f;
        #pragma unroll
        for (int i = 0; i < 8; i++) s += part[i];
        atomicAdd(&g_loss[q], s);
    }
    if (lane == 0) {
        int b = row >> 12, hw = row & 4095;
        out[OFF_IDX + ((size_t)((b << 2) + q))*4096 + hw] = (float)idx;
    }
}

// ============ transposed conv 4x4 s2 p1, 2x2 output-quad gather ============
template<int CI, int CO, int ACT>
__global__ void __launch_bounds__(256) convt_k4s2(const float* __restrict__ in,
        const float* __restrict__ w, const float* __restrict__ bias,
        float* __restrict__ out, int Hi, int Wi)
{
    __shared__ float ws[CI*16];
    int n = blockIdx.z / CO, co = blockIdx.z % CO;
    int tid = threadIdx.y*16 + threadIdx.x;
    for (int k = tid; k < CI*16; k += 256)
        ws[k] = __ldg(&w[(size_t)((k >> 4)*CO + co)*16 + (k & 15)]);
    __syncthreads();
    int i = blockIdx.y*16 + threadIdx.y - 1;
    int j = blockIdx.x*16 + threadIdx.x - 1;
    if (i > Hi-1 || j > Wi-1) return;
    int Ho = Hi*2, Wo = Wi*2;
    bool my0 = (i >= 0), my1 = (i < Hi-1);
    bool mx0 = (j >= 0), mx1 = (j < Wi-1);
    int ic = my0 ? i : 0, jc = mx0 ? j : 0;
    int off00 = ic*Wi + jc;
    int off01 = ic*Wi + (mx1 ? j+1 : jc);
    int off10 = (my1 ? i+1 : ic)*Wi + jc;
    int off11 = (my1 ? i+1 : ic)*Wi + (mx1 ? j+1 : jc);
    bool m00 = my0 && mx0, m01 = my0 && mx1, m10 = my1 && mx0, m11 = my1 && mx1;
    const float* p = in + (size_t)n*CI*Hi*Wi;
    float a00 = 0.f, a01 = 0.f, a10 = 0.f, a11 = 0.f;
    for (int ci = 0; ci < CI; ci++) {
        const float* wc = &ws[ci << 4];
        float v00 = m00 ? __ldg(p + off00) : 0.f;
        float v01 = m01 ? __ldg(p + off01) : 0.f;
        float v10 = m10 ? __ldg(p + off10) : 0.f;
        float v11 = m11 ? __ldg(p + off11) : 0.f;
        a00 += v00*wc[10] + v01*wc[8]  + v10*wc[2]  + v11*wc[0];
        a01 += v00*wc[11] + v01*wc[9]  + v10*wc[3]  + v11*wc[1];
        a10 += v00*wc[14] + v01*wc[12] + v10*wc[6]  + v11*wc[4];
        a11 += v00*wc[15] + v01*wc[13] + v10*wc[7]  + v11*wc[5];
        p += Hi*Wi;
    }
    float bv = __ldg(&bias[co]);
    a00 += bv; a01 += bv; a10 += bv; a11 += bv;
    if (ACT == 0) { a00=fmaxf(a00,0.f); a01=fmaxf(a01,0.f); a10=fmaxf(a10,0.f); a11=fmaxf(a11,0.f); }
    else { a00=tanhf(a00); a01=tanhf(a01); a10=tanhf(a10); a11=tanhf(a11); }
    float* ob = out + ((size_t)n*CO + co)*Ho*Wo;
    int oy0 = 2*i+1, ox0 = 2*j+1;
    bool wy0 = (oy0 >= 0), wy1 = (2*i+2 < Ho);
    bool wx0 = (ox0 >= 0), wx1 = (2*j+2 < Wo);
    if (wy0 && wx0) ob[oy0*Wo + ox0]         = a00;
    if (wy0 && wx1) ob[oy0*Wo + ox0+1]       = a01;
    if (wy1 && wx0) ob[(oy0+1)*Wo + ox0]     = a10;
    if (wy1 && wx1) ob[(oy0+1)*Wo + ox0+1]   = a11;
}

// ---------------- launch ----------------
extern "C" void kernel_launch(void* const* d_in, const int* in_sizes, int n_in,
                              void* d_out, int out_size)
{
    const float* x    = (const float*)d_in[0];
    const float* ew1  = (const float*)d_in[1];  const float* eb1 = (const float*)d_in[2];
    const float* ew2  = (const float*)d_in[3];  const float* eb2 = (const float*)d_in[4];
    const float* ew3  = (const float*)d_in[5];  const float* eb3 = (const float*)d_in[6];
    const float* ew4  = (const float*)d_in[7];  const float* eb4 = (const float*)d_in[8];
    const float* cbs  = (const float*)d_in[9];
    const float* dw1  = (const float*)d_in[10]; const float* db1 = (const float*)d_in[11];
    const float* dtw1 = (const float*)d_in[12]; const float* dtb1= (const float*)d_in[13];
    const float* dtw2 = (const float*)d_in[14]; const float* dtb2= (const float*)d_in[15];
    float* out = (float*)d_out;

    float *a1, *a2, *a3, *z, *quant, *d1, *dt1, *res;
    cudaGetSymbolAddress((void**)&a1,    g_a1);
    cudaGetSymbolAddress((void**)&a2,    g_a2);
    cudaGetSymbolAddress((void**)&a3,    g_a3);
    cudaGetSymbolAddress((void**)&z,     g_z);
    cudaGetSymbolAddress((void**)&res,   g_res);
    cudaGetSymbolAddress((void**)&quant, g_quant);
    cudaGetSymbolAddress((void**)&d1,    g_d1);
    cudaGetSymbolAddress((void**)&dt1,   g_dt1);

    dim3 b16(16, 16);

    // encoder
    conv_k4s2<3,  8><<<dim3(4, 4, BATCH*8 ), b16>>>(x,  ew1, eb1, a1, 256, 256, 128, 128, 64);
    conv_k4s2<64, 4><<<dim3(2, 2, BATCH*32), b16>>>(a1, ew2, eb2, a2, 128, 128,  64,  64, 128);
    conv3x3g<true ><<<dim3(2, 2, 32*BATCH), b16>>>(a2, ew3, eb3, a3, 128, 256);
    conv3x3g<false><<<dim3(2, 2, 32*BATCH), b16>>>(a3, ew4, eb4, z,  256, 256);

    // VQ
    nchw2nhwc<<<dim3(128, 8, BATCH), dim3(32, 8)>>>(z, res);
    cnorm_kernel<<<512, 256>>>(cbs);
    vq_init<<<1, 32>>>();
    pack_cb<<<QSTAGES*KCODES, 256>>>(cbs);
    for (int q = 0; q < QSTAGES; q++) {
        const float* cbq = cbs + (size_t)q * KCODES * D_LAT;
        reset_fix<<<1, 32>>>();
        vq_argmin_mma<<<NROWS/128, 256>>>(q);
        vq_fixup<<<64, 256>>>(cbq, q);
        vq_update<<<NROWS/8, 256>>>(cbq, out, q, q < QSTAGES-1 ? 1 : 0);
    }
    loss_final<<<1, 32>>>(out);
    nhwc2nchw<<<dim3(128, 8, BATCH), dim3(32, 8)>>>(quant, out + OFF_Q);

    // decoder
    conv3x3g<true><<<dim3(2, 2, 16*BATCH), b16>>>(out + OFF_Q, dw1, db1, d1, 256, 128);
    convt_k4s2<128, 64, 0><<<dim3(5, 5, BATCH*64), b16>>>(d1,  dtw1, dtb1, dt1, 64, 64);
    convt_k4s2<64,  3,  1><<<dim3(9, 9, BATCH*3 ), b16>>>(dt1, dtw2, dtb2, out + OFF_RECON, 128, 128);
}